// round 1
// baseline (speedup 1.0000x reference)
#include <cuda_runtime.h>
#include <float.h>

// Problem constants (fixed by reference setup_inputs)
#define LN   1024      // sequence length L
#define DD   768       // hidden d
#define HH   12        // heads
#define EE   32        // entities
#define MM   4         // mentions
#define RR   256       // relations per doc
#define NMAX 4         // batch

// Scratch (device globals -- no allocation allowed)
__device__ float g_e_emb[NMAX * EE * DD];            // (n,E,d)
__device__ float g_e_att[NMAX * EE * HH * LN];       // (n,E,h,L)
__device__ float g_ht_att[NMAX * RR * LN];           // (n,R,L)

// ---------------------------------------------------------------------------
// Kernel 1: e_emb[i,e,k] = logsumexp_m( mask>0 ? seq[i, pos+1, k] : -FLT_MAX )
// ---------------------------------------------------------------------------
__global__ void k_e_emb(const float* __restrict__ seq,
                        const int*   __restrict__ pos,
                        const float* __restrict__ mask,
                        int n)
{
    int idx = blockIdx.x * blockDim.x + threadIdx.x;
    int total = n * EE * DD;
    if (idx >= total) return;
    int k = idx % DD;
    int e = (idx / DD) % EE;
    int i = idx / (DD * EE);

    const int*   p  = pos  + (i * EE + e) * MM;
    const float* mk = mask + (i * EE + e) * MM;

    float v[MM];
    float mx = -FLT_MAX;
#pragma unroll
    for (int m = 0; m < MM; m++) {
        int pp = p[m] + 1;                       // OFFSET
        float x = seq[(i * LN + pp) * DD + k];
        if (mk[m] <= 0.0f) x = -FLT_MAX;
        v[m] = x;
        mx = fmaxf(mx, x);
    }
    float s = 0.0f;
#pragma unroll
    for (int m = 0; m < MM; m++) s += expf(v[m] - mx);
    g_e_emb[idx] = mx + logf(s);
}

// ---------------------------------------------------------------------------
// Kernel 2: e_att[i,e,hh,l] = sum_m mask*att[i,hh,pos+1,l] / max(sum_m mask, 1)
// ---------------------------------------------------------------------------
__global__ void k_e_att(const float* __restrict__ att,
                        const int*   __restrict__ pos,
                        const float* __restrict__ mask,
                        int n)
{
    int idx = blockIdx.x * blockDim.x + threadIdx.x;
    int total = n * EE * HH * LN;
    if (idx >= total) return;
    int l  = idx % LN;
    int hh = (idx / LN) % HH;
    int e  = (idx / (LN * HH)) % EE;
    int i  = idx / (LN * HH * EE);

    const int*   p  = pos  + (i * EE + e) * MM;
    const float* mk = mask + (i * EE + e) * MM;

    float cnt = 0.0f, s = 0.0f;
#pragma unroll
    for (int m = 0; m < MM; m++) {
        float mm = mk[m];
        cnt += mm;
        int pp = p[m] + 1;
        s += mm * att[((size_t)(i * HH + hh) * LN + pp) * LN + l];
    }
    cnt = fmaxf(cnt, 1.0f);
    g_e_att[idx] = s / cnt;
}

// ---------------------------------------------------------------------------
// Kernel 3: one block per (i,r).
// ht[l] = (1/H) sum_h eA[h,l]*eB[h,l];  ht /= (sum_l ht + 1e-5)
// ---------------------------------------------------------------------------
__global__ void k_ht_att(const int* __restrict__ hts, int n)
{
    int b = blockIdx.x;               // i*R + r
    int i = b / RR;
    int ha = hts[b * 2 + 0];
    int ta = hts[b * 2 + 1];

    const float* A = g_e_att + (size_t)(i * EE + ha) * HH * LN;
    const float* B = g_e_att + (size_t)(i * EE + ta) * HH * LN;

    const float invH = 1.0f / (float)HH;
    float v[LN / 256];
    float local = 0.0f;
#pragma unroll
    for (int j = 0; j < LN / 256; j++) {
        int l = threadIdx.x + j * 256;
        float s = 0.0f;
#pragma unroll
        for (int hh = 0; hh < HH; hh++)
            s += A[hh * LN + l] * B[hh * LN + l];
        v[j] = s * invH;
        local += v[j];
    }

    // block reduce
    __shared__ float red[8];
#pragma unroll
    for (int off = 16; off > 0; off >>= 1)
        local += __shfl_xor_sync(0xffffffffu, local, off);
    if ((threadIdx.x & 31) == 0) red[threadIdx.x >> 5] = local;
    __syncthreads();
    float tot;
    if (threadIdx.x < 32) {
        float x = (threadIdx.x < 8) ? red[threadIdx.x] : 0.0f;
#pragma unroll
        for (int off = 4; off > 0; off >>= 1)
            x += __shfl_xor_sync(0xffffffffu, x, off);
        if (threadIdx.x == 0) red[0] = x;
    }
    __syncthreads();
    tot = red[0];
    float inv = 1.0f / (tot + 1e-5f);

    float* dst = g_ht_att + (size_t)b * LN;
#pragma unroll
    for (int j = 0; j < LN / 256; j++) {
        int l = threadIdx.x + j * 256;
        dst[l] = v[j] * inv;
    }
}

// ---------------------------------------------------------------------------
// Kernel 4: hs / ts planes of output
// out[0, i*R+r, k] = e_emb[i, hts[..,0], k];  out[1, ...] = tail
// ---------------------------------------------------------------------------
__global__ void k_hsts(const int* __restrict__ hts, float* __restrict__ out, int n)
{
    int idx = blockIdx.x * blockDim.x + threadIdx.x;
    int total = n * RR * DD;
    if (idx >= total) return;
    int k = idx % DD;
    int b = idx / DD;           // i*R + r
    int i = b / RR;
    int ha = hts[b * 2 + 0];
    int ta = hts[b * 2 + 1];
    size_t P = (size_t)n * RR * DD;
    out[idx]     = g_e_emb[(size_t)(i * EE + ha) * DD + k];
    out[P + idx] = g_e_emb[(size_t)(i * EE + ta) * DD + k];
}

// ---------------------------------------------------------------------------
// Kernel 5: rs plane. Batched SGEMM: C(i) [R x D] = ht_att(i) [R x L] * seq(i) [L x D]
// BM=64 BN=64 BK=16, 256 threads, 4x4 per thread.
// ---------------------------------------------------------------------------
#define BM 64
#define BN 64
#define BK 16

__global__ __launch_bounds__(256) void k_gemm(const float* __restrict__ seq,
                                              float* __restrict__ out, int n)
{
    int i = blockIdx.z;
    const float* Ad = g_ht_att + (size_t)i * RR * LN;   // R x L
    const float* Bd = seq      + (size_t)i * LN * DD;   // L x D
    size_t P = (size_t)n * RR * DD;
    float* Cd = out + 2 * P + (size_t)i * RR * DD;      // R x D

    int rowBase = blockIdx.y * BM;
    int colBase = blockIdx.x * BN;

    __shared__ float As[BK][BM];
    __shared__ float Bs[BK][BN];

    int tx = threadIdx.x & 15;
    int ty = threadIdx.x >> 4;
    int tid = threadIdx.x;

    int aRow = tid >> 2;            // 0..63
    int aK4  = (tid & 3) * 4;       // 0,4,8,12
    int bK   = tid >> 4;            // 0..15
    int bC4  = (tid & 15) * 4;      // 0..60

    float acc[4][4];
#pragma unroll
    for (int m = 0; m < 4; m++)
#pragma unroll
        for (int c = 0; c < 4; c++) acc[m][c] = 0.0f;

    for (int k0 = 0; k0 < LN; k0 += BK) {
        float4 a = *(const float4*)&Ad[(size_t)(rowBase + aRow) * LN + k0 + aK4];
        As[aK4 + 0][aRow] = a.x;
        As[aK4 + 1][aRow] = a.y;
        As[aK4 + 2][aRow] = a.z;
        As[aK4 + 3][aRow] = a.w;
        float4 b = *(const float4*)&Bd[(size_t)(k0 + bK) * DD + colBase + bC4];
        *(float4*)&Bs[bK][bC4] = b;
        __syncthreads();

#pragma unroll
        for (int kk = 0; kk < BK; kk++) {
            float4 ar4 = *(const float4*)&As[kk][ty * 4];
            float4 br4 = *(const float4*)&Bs[kk][tx * 4];
            float ar[4] = {ar4.x, ar4.y, ar4.z, ar4.w};
            float br[4] = {br4.x, br4.y, br4.z, br4.w};
#pragma unroll
            for (int m = 0; m < 4; m++)
#pragma unroll
                for (int c = 0; c < 4; c++)
                    acc[m][c] = fmaf(ar[m], br[c], acc[m][c]);
        }
        __syncthreads();
    }

#pragma unroll
    for (int m = 0; m < 4; m++) {
        float4 o = {acc[m][0], acc[m][1], acc[m][2], acc[m][3]};
        *(float4*)&Cd[(size_t)(rowBase + ty * 4 + m) * DD + colBase + tx * 4] = o;
    }
}

// ---------------------------------------------------------------------------
extern "C" void kernel_launch(void* const* d_in, const int* in_sizes, int n_in,
                              void* d_out, int out_size)
{
    const float* seq  = (const float*)d_in[0];   // (n, L, d)
    const float* att  = (const float*)d_in[1];   // (n, h, L, L)
    const int*   pos  = (const int*)  d_in[2];   // (n, E, M)
    const float* mask = (const float*)d_in[3];   // (n, E, M)
    const int*   hts  = (const int*)  d_in[4];   // (n, R, 2)
    float* out = (float*)d_out;

    int n = in_sizes[0] / (LN * DD);
    if (n > NMAX) n = NMAX;

    {   // e_emb
        int total = n * EE * DD;
        k_e_emb<<<(total + 255) / 256, 256>>>(seq, pos, mask, n);
    }
    {   // e_att
        int total = n * EE * HH * LN;
        k_e_att<<<(total + 255) / 256, 256>>>(att, pos, mask, n);
    }
    {   // ht_att
        k_ht_att<<<n * RR, 256>>>(hts, n);
    }
    {   // hs/ts planes
        int total = n * RR * DD;
        k_hsts<<<(total + 255) / 256, 256>>>(hts, out, n);
    }
    {   // rs plane GEMM
        dim3 grid(DD / BN, RR / BM, n);
        k_gemm<<<grid, 256>>>(seq, out, n);
    }
}

// round 2
// speedup vs baseline: 1.3388x; 1.3388x over previous
#include <cuda_runtime.h>
#include <float.h>

// Problem constants (fixed by reference setup_inputs)
#define LN   1024      // sequence length L
#define DD   768       // hidden d
#define HH   12        // heads
#define EE   32        // entities
#define MM   4         // mentions
#define RR   256       // relations per doc
#define NMAX 4         // batch

// Scratch (device globals -- no allocation allowed)
__device__ float g_e_emb[NMAX * EE * DD];            // (n,E,d)
__device__ float g_e_att[NMAX * EE * HH * LN];       // (n,E,h,L)
__device__ float g_ht_att[NMAX * RR * LN];           // (n,R,L)

// ---------------------------------------------------------------------------
// f32x2 helpers
// ---------------------------------------------------------------------------
__device__ __forceinline__ void ffma2(unsigned long long& d,
                                      unsigned long long a,
                                      unsigned long long b)
{
    asm("fma.rn.f32x2 %0, %1, %2, %0;" : "+l"(d) : "l"(a), "l"(b));
}
__device__ __forceinline__ unsigned long long bcast2(float x)
{
    unsigned long long r;
    asm("mov.b64 %0, {%1, %1};" : "=l"(r) : "f"(x));
    return r;
}
__device__ __forceinline__ float lo32(unsigned long long v)
{
    return __uint_as_float((unsigned)(v & 0xffffffffull));
}
__device__ __forceinline__ float hi32(unsigned long long v)
{
    return __uint_as_float((unsigned)(v >> 32));
}

// ---------------------------------------------------------------------------
// Kernel 1: e_emb[i,e,k] = logsumexp_m( mask>0 ? seq[i, pos+1, k] : -FLT_MAX )
// ---------------------------------------------------------------------------
__global__ void k_e_emb(const float* __restrict__ seq,
                        const int*   __restrict__ pos,
                        const float* __restrict__ mask,
                        int n)
{
    int idx = blockIdx.x * blockDim.x + threadIdx.x;
    int total = n * EE * DD;
    if (idx >= total) return;
    int k = idx % DD;
    int e = (idx / DD) % EE;
    int i = idx / (DD * EE);

    const int*   p  = pos  + (i * EE + e) * MM;
    const float* mk = mask + (i * EE + e) * MM;

    float v[MM];
    float mx = -FLT_MAX;
#pragma unroll
    for (int m = 0; m < MM; m++) {
        int pp = p[m] + 1;                       // OFFSET
        float x = seq[(i * LN + pp) * DD + k];
        if (mk[m] <= 0.0f) x = -FLT_MAX;
        v[m] = x;
        mx = fmaxf(mx, x);
    }
    float s = 0.0f;
#pragma unroll
    for (int m = 0; m < MM; m++) s += expf(v[m] - mx);
    g_e_emb[idx] = mx + logf(s);
}

// ---------------------------------------------------------------------------
// Kernel 2 (float4): e_att[i,e,hh,l] = sum_m mask*att[i,hh,pos+1,l] / cnt
// ---------------------------------------------------------------------------
__global__ void k_e_att(const float* __restrict__ att,
                        const int*   __restrict__ pos,
                        const float* __restrict__ mask,
                        int n)
{
    int idx = blockIdx.x * blockDim.x + threadIdx.x;     // over float4 elems
    int total = n * EE * HH * (LN / 4);
    if (idx >= total) return;
    int l4 = idx % (LN / 4);
    int hh = (idx / (LN / 4)) % HH;
    int e  = (idx / ((LN / 4) * HH)) % EE;
    int i  = idx / ((LN / 4) * HH * EE);

    const int*   p  = pos  + (i * EE + e) * MM;
    const float* mk = mask + (i * EE + e) * MM;
    const float4* att4 = (const float4*)att;

    float cnt = 0.0f;
    float4 s = make_float4(0.f, 0.f, 0.f, 0.f);
#pragma unroll
    for (int m = 0; m < MM; m++) {
        float mm = mk[m];
        cnt += mm;
        int pp = p[m] + 1;
        float4 a = att4[((size_t)(i * HH + hh) * LN + pp) * (LN / 4) + l4];
        s.x += mm * a.x; s.y += mm * a.y; s.z += mm * a.z; s.w += mm * a.w;
    }
    float inv = 1.0f / fmaxf(cnt, 1.0f);
    s.x *= inv; s.y *= inv; s.z *= inv; s.w *= inv;
    ((float4*)g_e_att)[idx] = s;
}

// ---------------------------------------------------------------------------
// Kernel 3 (float4): one block (256 thr) per (i,r).
// ht[l] = (1/H) sum_h eA[h,l]*eB[h,l];  ht /= (sum_l ht + 1e-5)
// ---------------------------------------------------------------------------
__global__ void k_ht_att(const int* __restrict__ hts, int n)
{
    int b = blockIdx.x;               // i*R + r
    int i = b / RR;
    int ha = hts[b * 2 + 0];
    int ta = hts[b * 2 + 1];

    const float4* A = (const float4*)(g_e_att + (size_t)(i * EE + ha) * HH * LN);
    const float4* B = (const float4*)(g_e_att + (size_t)(i * EE + ta) * HH * LN);
    int t = threadIdx.x;              // 256 threads, one float4 each

    float4 s = make_float4(0.f, 0.f, 0.f, 0.f);
#pragma unroll
    for (int hh = 0; hh < HH; hh++) {
        float4 a = A[hh * (LN / 4) + t];
        float4 c = B[hh * (LN / 4) + t];
        s.x += a.x * c.x; s.y += a.y * c.y; s.z += a.z * c.z; s.w += a.w * c.w;
    }
    const float invH = 1.0f / (float)HH;
    s.x *= invH; s.y *= invH; s.z *= invH; s.w *= invH;
    float local = s.x + s.y + s.z + s.w;

    __shared__ float red[8];
#pragma unroll
    for (int off = 16; off > 0; off >>= 1)
        local += __shfl_xor_sync(0xffffffffu, local, off);
    if ((t & 31) == 0) red[t >> 5] = local;
    __syncthreads();
    if (t < 32) {
        float x = (t < 8) ? red[t] : 0.0f;
#pragma unroll
        for (int off = 4; off > 0; off >>= 1)
            x += __shfl_xor_sync(0xffffffffu, x, off);
        if (t == 0) red[0] = x;
    }
    __syncthreads();
    float inv = 1.0f / (red[0] + 1e-5f);

    float4 o = make_float4(s.x * inv, s.y * inv, s.z * inv, s.w * inv);
    ((float4*)(g_ht_att + (size_t)b * LN))[t] = o;
}

// ---------------------------------------------------------------------------
// Kernel 4 (float4): hs / ts planes of output
// ---------------------------------------------------------------------------
__global__ void k_hsts(const int* __restrict__ hts, float* __restrict__ out, int n)
{
    int idx = blockIdx.x * blockDim.x + threadIdx.x;     // over float4
    int total = n * RR * (DD / 4);
    if (idx >= total) return;
    int k4 = idx % (DD / 4);
    int b  = idx / (DD / 4);           // i*R + r
    int i  = b / RR;
    int ha = hts[b * 2 + 0];
    int ta = hts[b * 2 + 1];
    size_t P4 = (size_t)n * RR * (DD / 4);
    const float4* emb4 = (const float4*)g_e_emb;
    float4* out4 = (float4*)out;
    out4[idx]      = emb4[(size_t)(i * EE + ha) * (DD / 4) + k4];
    out4[P4 + idx] = emb4[(size_t)(i * EE + ta) * (DD / 4) + k4];
}

// ---------------------------------------------------------------------------
// Kernel 5: rs plane. Batched SGEMM with packed f32x2 FMA.
// C(i) [R x D] = ht_att(i) [R x L] * seq(i) [L x D]
// BM=64 BN=96 BK=32, 192 threads, thread tile 8 rows x 4 cols
// (accumulators packed pairwise along rows). grid = 8 x 4 x 4 = 128 blocks
// (single wave on 148 SMs). Register-prefetch + double-buffered smem,
// one __syncthreads per K-iter.
// ---------------------------------------------------------------------------
#define BMg 64
#define BNg 96
#define BKg 32
#define GT  192

__global__ __launch_bounds__(GT) void k_gemm(const float* __restrict__ seq,
                                             float* __restrict__ out, int n)
{
    __shared__ __align__(16) float As[2][BKg][BMg + 4];   // [k][m], transposed A
    __shared__ __align__(16) float Bs[2][BKg][BNg + 4];   // [k][n]

    int i = blockIdx.z;
    const float* Ad = g_ht_att + (size_t)i * RR * LN;   // R x L
    const float* Bd = seq      + (size_t)i * LN * DD;   // L x D
    size_t P = (size_t)n * RR * DD;
    float* Cd = out + 2 * P + (size_t)i * RR * DD;      // R x D

    int rowBase = blockIdx.y * BMg;
    int colBase = blockIdx.x * BNg;
    int tid = threadIdx.x;

    // ---- loader slots ----
    // A tile: 64 rows x 32 k = 512 float4 (4 k's each); idx = tid + s*192
    int aRow0 = tid >> 3,          aK0 = (tid & 7) * 4;
    int i1 = tid + GT;  int aRow1 = i1 >> 3,  aK1 = (i1 & 7) * 4;
    int i2 = tid + 2 * GT; int aRow2 = i2 >> 3, aK2 = (i2 & 7) * 4;
    bool has2 = (i2 < 512);
    // B tile: 32 k x 96 cols = 768 float4; idx = tid + s*192 (exact)
    int bRow[4], bC[4];
#pragma unroll
    for (int s = 0; s < 4; s++) {
        int id = tid + s * GT;
        bRow[s] = id / 24;
        bC[s]   = (id % 24) * 4;
    }

    // ---- compute mapping: 8 rows (ty) x 4 cols (tx) per thread ----
    int ty = tid / 24;     // 0..7  -> rows ty*8 .. ty*8+7
    int tx = tid % 24;     // 0..23 -> cols tx*4 .. tx*4+3

    unsigned long long acc[4][4];   // [row-pair][col]
#pragma unroll
    for (int rp = 0; rp < 4; rp++)
#pragma unroll
        for (int c = 0; c < 4; c++) acc[rp][c] = 0ull;

    // ---- initial global loads (k0 = 0) ----
    float4 ra0, ra1, ra2, rb[4];
    ra0 = *(const float4*)&Ad[(size_t)(rowBase + aRow0) * LN + aK0];
    ra1 = *(const float4*)&Ad[(size_t)(rowBase + aRow1) * LN + aK1];
    if (has2) ra2 = *(const float4*)&Ad[(size_t)(rowBase + aRow2) * LN + aK2];
#pragma unroll
    for (int s = 0; s < 4; s++)
        rb[s] = *(const float4*)&Bd[(size_t)bRow[s] * DD + colBase + bC[s]];

    int buf = 0;
    for (int k0 = 0; k0 < LN; k0 += BKg) {
        // store prefetched regs into smem buffer `buf`
        As[buf][aK0 + 0][aRow0] = ra0.x;
        As[buf][aK0 + 1][aRow0] = ra0.y;
        As[buf][aK0 + 2][aRow0] = ra0.z;
        As[buf][aK0 + 3][aRow0] = ra0.w;
        As[buf][aK1 + 0][aRow1] = ra1.x;
        As[buf][aK1 + 1][aRow1] = ra1.y;
        As[buf][aK1 + 2][aRow1] = ra1.z;
        As[buf][aK1 + 3][aRow1] = ra1.w;
        if (has2) {
            As[buf][aK2 + 0][aRow2] = ra2.x;
            As[buf][aK2 + 1][aRow2] = ra2.y;
            As[buf][aK2 + 2][aRow2] = ra2.z;
            As[buf][aK2 + 3][aRow2] = ra2.w;
        }
#pragma unroll
        for (int s = 0; s < 4; s++)
            *(float4*)&Bs[buf][bRow[s]][bC[s]] = rb[s];
        __syncthreads();

        // prefetch next K-slab into registers (hidden under compute)
        int kn = k0 + BKg;
        if (kn < LN) {
            ra0 = *(const float4*)&Ad[(size_t)(rowBase + aRow0) * LN + kn + aK0];
            ra1 = *(const float4*)&Ad[(size_t)(rowBase + aRow1) * LN + kn + aK1];
            if (has2) ra2 = *(const float4*)&Ad[(size_t)(rowBase + aRow2) * LN + kn + aK2];
#pragma unroll
            for (int s = 0; s < 4; s++)
                rb[s] = *(const float4*)&Bd[(size_t)(kn + bRow[s]) * DD + colBase + bC[s]];
        }

        // compute on buffer `buf`
#pragma unroll
        for (int kk = 0; kk < BKg; kk++) {
            const float* ap = &As[buf][kk][ty * 8];
            unsigned long long a0 = *(const unsigned long long*)(ap + 0);
            unsigned long long a1 = *(const unsigned long long*)(ap + 2);
            unsigned long long a2 = *(const unsigned long long*)(ap + 4);
            unsigned long long a3 = *(const unsigned long long*)(ap + 6);
            float4 b4 = *(const float4*)&Bs[buf][kk][tx * 4];
            unsigned long long b0 = bcast2(b4.x);
            unsigned long long b1 = bcast2(b4.y);
            unsigned long long b2 = bcast2(b4.z);
            unsigned long long b3 = bcast2(b4.w);
            ffma2(acc[0][0], a0, b0); ffma2(acc[0][1], a0, b1);
            ffma2(acc[0][2], a0, b2); ffma2(acc[0][3], a0, b3);
            ffma2(acc[1][0], a1, b0); ffma2(acc[1][1], a1, b1);
            ffma2(acc[1][2], a1, b2); ffma2(acc[1][3], a1, b3);
            ffma2(acc[2][0], a2, b0); ffma2(acc[2][1], a2, b1);
            ffma2(acc[2][2], a2, b2); ffma2(acc[2][3], a2, b3);
            ffma2(acc[3][0], a3, b0); ffma2(acc[3][1], a3, b1);
            ffma2(acc[3][2], a3, b2); ffma2(acc[3][3], a3, b3);
        }
        buf ^= 1;
        __syncthreads();
    }

    // ---- epilogue: rows ty*8+2rp (lo) and ty*8+2rp+1 (hi), cols tx*4..+3 ----
#pragma unroll
    for (int rp = 0; rp < 4; rp++) {
        int r0 = rowBase + ty * 8 + rp * 2;
        float4 vlo = make_float4(lo32(acc[rp][0]), lo32(acc[rp][1]),
                                 lo32(acc[rp][2]), lo32(acc[rp][3]));
        float4 vhi = make_float4(hi32(acc[rp][0]), hi32(acc[rp][1]),
                                 hi32(acc[rp][2]), hi32(acc[rp][3]));
        *(float4*)&Cd[(size_t)r0 * DD + colBase + tx * 4]       = vlo;
        *(float4*)&Cd[(size_t)(r0 + 1) * DD + colBase + tx * 4] = vhi;
    }
}

// ---------------------------------------------------------------------------
extern "C" void kernel_launch(void* const* d_in, const int* in_sizes, int n_in,
                              void* d_out, int out_size)
{
    const float* seq  = (const float*)d_in[0];   // (n, L, d)
    const float* att  = (const float*)d_in[1];   // (n, h, L, L)
    const int*   pos  = (const int*)  d_in[2];   // (n, E, M)
    const float* mask = (const float*)d_in[3];   // (n, E, M)
    const int*   hts  = (const int*)  d_in[4];   // (n, R, 2)
    float* out = (float*)d_out;

    int n = in_sizes[0] / (LN * DD);
    if (n > NMAX) n = NMAX;

    {   // e_emb
        int total = n * EE * DD;
        k_e_emb<<<(total + 255) / 256, 256>>>(seq, pos, mask, n);
    }
    {   // e_att (float4)
        int total = n * EE * HH * (LN / 4);
        k_e_att<<<(total + 255) / 256, 256>>>(att, pos, mask, n);
    }
    {   // ht_att
        k_ht_att<<<n * RR, 256>>>(hts, n);
    }
    {   // hs/ts planes (float4)
        int total = n * RR * (DD / 4);
        k_hsts<<<(total + 255) / 256, 256>>>(hts, out, n);
    }
    {   // rs plane GEMM (f32x2)
        dim3 grid(DD / BNg, RR / BMg, n);
        k_gemm<<<grid, GT>>>(seq, out, n);
    }
}

// round 3
// speedup vs baseline: 1.6466x; 1.2299x over previous
#include <cuda_runtime.h>
#include <float.h>

// Problem constants (fixed by reference setup_inputs)
#define LN   1024      // sequence length L
#define DD   768       // hidden d
#define HH   12        // heads
#define EE   32        // entities
#define MM   4         // mentions
#define RR   256       // relations per doc
#define NMAX 4         // batch

// Scratch (device globals -- no allocation allowed)
__device__ float g_e_emb[NMAX * EE * DD];            // (n,E,d)
__device__ float g_e_att[NMAX * EE * HH * LN];       // (n,E,h,L)
__device__ float g_ht_att[NMAX * RR * LN];           // (n,R,L)

// ---------------------------------------------------------------------------
// f32x2 helpers
// ---------------------------------------------------------------------------
__device__ __forceinline__ void ffma2(unsigned long long& d,
                                      unsigned long long a,
                                      unsigned long long b)
{
    asm("fma.rn.f32x2 %0, %1, %2, %0;" : "+l"(d) : "l"(a), "l"(b));
}
__device__ __forceinline__ unsigned long long bcast2(float x)
{
    unsigned long long r;
    asm("mov.b64 %0, {%1, %1};" : "=l"(r) : "f"(x));
    return r;
}
__device__ __forceinline__ float lo32(unsigned long long v)
{
    return __uint_as_float((unsigned)(v & 0xffffffffull));
}
__device__ __forceinline__ float hi32(unsigned long long v)
{
    return __uint_as_float((unsigned)(v >> 32));
}

// ---------------------------------------------------------------------------
// Kernel 1: e_emb[i,e,k] = logsumexp_m( mask>0 ? seq[i, pos+1, k] : -FLT_MAX )
// ---------------------------------------------------------------------------
__global__ void k_e_emb(const float* __restrict__ seq,
                        const int*   __restrict__ pos,
                        const float* __restrict__ mask,
                        int n)
{
    int idx = blockIdx.x * blockDim.x + threadIdx.x;
    int total = n * EE * DD;
    if (idx >= total) return;
    int k = idx % DD;
    int e = (idx / DD) % EE;
    int i = idx / (DD * EE);

    const int*   p  = pos  + (i * EE + e) * MM;
    const float* mk = mask + (i * EE + e) * MM;

    float v[MM];
    float mx = -FLT_MAX;
#pragma unroll
    for (int m = 0; m < MM; m++) {
        int pp = p[m] + 1;                       // OFFSET
        float x = seq[(i * LN + pp) * DD + k];
        if (mk[m] <= 0.0f) x = -FLT_MAX;
        v[m] = x;
        mx = fmaxf(mx, x);
    }
    float s = 0.0f;
#pragma unroll
    for (int m = 0; m < MM; m++) s += expf(v[m] - mx);
    g_e_emb[idx] = mx + logf(s);
}

// ---------------------------------------------------------------------------
// Kernel 2 (float4): e_att[i,e,hh,l] = sum_m mask*att[i,hh,pos+1,l] / cnt
// ---------------------------------------------------------------------------
__global__ void k_e_att(const float* __restrict__ att,
                        const int*   __restrict__ pos,
                        const float* __restrict__ mask,
                        int n)
{
    int idx = blockIdx.x * blockDim.x + threadIdx.x;     // over float4 elems
    int total = n * EE * HH * (LN / 4);
    if (idx >= total) return;
    int l4 = idx % (LN / 4);
    int hh = (idx / (LN / 4)) % HH;
    int e  = (idx / ((LN / 4) * HH)) % EE;
    int i  = idx / ((LN / 4) * HH * EE);

    const int*   p  = pos  + (i * EE + e) * MM;
    const float* mk = mask + (i * EE + e) * MM;
    const float4* att4 = (const float4*)att;

    float cnt = 0.0f;
    float4 s = make_float4(0.f, 0.f, 0.f, 0.f);
#pragma unroll
    for (int m = 0; m < MM; m++) {
        float mm = mk[m];
        cnt += mm;
        int pp = p[m] + 1;
        float4 a = att4[((size_t)(i * HH + hh) * LN + pp) * (LN / 4) + l4];
        s.x += mm * a.x; s.y += mm * a.y; s.z += mm * a.z; s.w += mm * a.w;
    }
    float inv = 1.0f / fmaxf(cnt, 1.0f);
    s.x *= inv; s.y *= inv; s.z *= inv; s.w *= inv;
    ((float4*)g_e_att)[idx] = s;
}

// ---------------------------------------------------------------------------
// Kernel 3 (float4): one block (256 thr) per (i,r).
// ht[l] = (1/H) sum_h eA[h,l]*eB[h,l];  ht /= (sum_l ht + 1e-5)
// ---------------------------------------------------------------------------
__global__ void k_ht_att(const int* __restrict__ hts, int n)
{
    int b = blockIdx.x;               // i*R + r
    int i = b / RR;
    int ha = hts[b * 2 + 0];
    int ta = hts[b * 2 + 1];

    const float4* A = (const float4*)(g_e_att + (size_t)(i * EE + ha) * HH * LN);
    const float4* B = (const float4*)(g_e_att + (size_t)(i * EE + ta) * HH * LN);
    int t = threadIdx.x;              // 256 threads, one float4 each

    float4 s = make_float4(0.f, 0.f, 0.f, 0.f);
#pragma unroll
    for (int hh = 0; hh < HH; hh++) {
        float4 a = A[hh * (LN / 4) + t];
        float4 c = B[hh * (LN / 4) + t];
        s.x += a.x * c.x; s.y += a.y * c.y; s.z += a.z * c.z; s.w += a.w * c.w;
    }
    const float invH = 1.0f / (float)HH;
    s.x *= invH; s.y *= invH; s.z *= invH; s.w *= invH;
    float local = s.x + s.y + s.z + s.w;

    __shared__ float red[8];
#pragma unroll
    for (int off = 16; off > 0; off >>= 1)
        local += __shfl_xor_sync(0xffffffffu, local, off);
    if ((t & 31) == 0) red[t >> 5] = local;
    __syncthreads();
    if (t < 32) {
        float x = (t < 8) ? red[t] : 0.0f;
#pragma unroll
        for (int off = 4; off > 0; off >>= 1)
            x += __shfl_xor_sync(0xffffffffu, x, off);
        if (t == 0) red[0] = x;
    }
    __syncthreads();
    float inv = 1.0f / (red[0] + 1e-5f);

    float4 o = make_float4(s.x * inv, s.y * inv, s.z * inv, s.w * inv);
    ((float4*)(g_ht_att + (size_t)b * LN))[t] = o;
}

// ---------------------------------------------------------------------------
// Kernel 4: rs plane SGEMM (f32x2) + fused hs/ts plane copy.
// C(i) [R x D] = ht_att(i) [R x L] * seq(i) [L x D]
// BM=64 BN=96 BK=32, 256 threads (8 warps, balanced 2/SMSP),
// per-thread tile 4 rows x 6 cols (2 f32x2 row-pairs).
// grid = 8 x 4 x 4 = 128 blocks -> single wave on 148 SMs.
// Each block also copies its 64x96 tile of the hs/ts output planes
// (gather from g_e_emb via hts), replacing the separate k_hsts kernel.
// ---------------------------------------------------------------------------
#define BMg 64
#define BNg 96
#define BKg 32
#define GT  256

__global__ __launch_bounds__(GT) void k_gemm(const float* __restrict__ seq,
                                             const int*   __restrict__ hts,
                                             float* __restrict__ out, int n)
{
    __shared__ __align__(16) float As[2][BKg][BMg + 2];   // [k][m], transposed A
    __shared__ __align__(16) float Bs[2][BKg][BNg + 4];   // [k][n]

    int i = blockIdx.z;
    const float* Ad = g_ht_att + (size_t)i * RR * LN;   // R x L
    const float* Bd = seq      + (size_t)i * LN * DD;   // L x D
    size_t P = (size_t)n * RR * DD;
    float* Cd = out + 2 * P + (size_t)i * RR * DD;      // R x D

    int rowBase = blockIdx.y * BMg;
    int colBase = blockIdx.x * BNg;
    int tid = threadIdx.x;

    // ---- loader slots ----
    // A tile: 64 rows x 32 k = 512 float4; 2 per thread
    int aRow0 = tid >> 3,            aK0 = (tid & 7) * 4;
    int i1 = tid + GT; int aRow1 = i1 >> 3, aK1 = (i1 & 7) * 4;
    // B tile: 32 k x 96 cols = 768 float4; 3 per thread
    int bRow[3], bC[3];
#pragma unroll
    for (int s = 0; s < 3; s++) {
        int id = tid + s * GT;
        bRow[s] = id / 24;
        bC[s]   = (id % 24) * 4;
    }

    // ---- compute mapping: 4 rows (ty) x 6 cols (tx) per thread ----
    int ty = tid >> 4;     // 0..15 -> rows ty*4 .. ty*4+3
    int tx = tid & 15;     // 0..15 -> cols tx*6 .. tx*6+5

    unsigned long long acc[2][6];   // [row-pair][col]
#pragma unroll
    for (int rp = 0; rp < 2; rp++)
#pragma unroll
        for (int c = 0; c < 6; c++) acc[rp][c] = 0ull;

    // ---- initial global loads (k0 = 0) ----
    float4 ra0, ra1, rb[3];
    ra0 = *(const float4*)&Ad[(size_t)(rowBase + aRow0) * LN + aK0];
    ra1 = *(const float4*)&Ad[(size_t)(rowBase + aRow1) * LN + aK1];
#pragma unroll
    for (int s = 0; s < 3; s++)
        rb[s] = *(const float4*)&Bd[(size_t)bRow[s] * DD + colBase + bC[s]];

    int buf = 0;
    for (int k0 = 0; k0 < LN; k0 += BKg) {
        // store prefetched regs into smem buffer `buf`
        As[buf][aK0 + 0][aRow0] = ra0.x;
        As[buf][aK0 + 1][aRow0] = ra0.y;
        As[buf][aK0 + 2][aRow0] = ra0.z;
        As[buf][aK0 + 3][aRow0] = ra0.w;
        As[buf][aK1 + 0][aRow1] = ra1.x;
        As[buf][aK1 + 1][aRow1] = ra1.y;
        As[buf][aK1 + 2][aRow1] = ra1.z;
        As[buf][aK1 + 3][aRow1] = ra1.w;
#pragma unroll
        for (int s = 0; s < 3; s++)
            *(float4*)&Bs[buf][bRow[s]][bC[s]] = rb[s];
        __syncthreads();

        // prefetch next K-slab into registers (hidden under compute)
        int kn = k0 + BKg;
        if (kn < LN) {
            ra0 = *(const float4*)&Ad[(size_t)(rowBase + aRow0) * LN + kn + aK0];
            ra1 = *(const float4*)&Ad[(size_t)(rowBase + aRow1) * LN + kn + aK1];
#pragma unroll
            for (int s = 0; s < 3; s++)
                rb[s] = *(const float4*)&Bd[(size_t)(kn + bRow[s]) * DD + colBase + bC[s]];
        }

        // compute on buffer `buf`
#pragma unroll
        for (int kk = 0; kk < BKg; kk++) {
            const float* ap = &As[buf][kk][ty * 4];
            unsigned long long a0 = *(const unsigned long long*)(ap + 0);
            unsigned long long a1 = *(const unsigned long long*)(ap + 2);
            const float* bp = &Bs[buf][kk][tx * 6];
            float2 b01 = *(const float2*)(bp + 0);
            float2 b23 = *(const float2*)(bp + 2);
            float2 b45 = *(const float2*)(bp + 4);
            unsigned long long bb0 = bcast2(b01.x);
            unsigned long long bb1 = bcast2(b01.y);
            unsigned long long bb2 = bcast2(b23.x);
            unsigned long long bb3 = bcast2(b23.y);
            unsigned long long bb4 = bcast2(b45.x);
            unsigned long long bb5 = bcast2(b45.y);
            ffma2(acc[0][0], a0, bb0); ffma2(acc[0][1], a0, bb1);
            ffma2(acc[0][2], a0, bb2); ffma2(acc[0][3], a0, bb3);
            ffma2(acc[0][4], a0, bb4); ffma2(acc[0][5], a0, bb5);
            ffma2(acc[1][0], a1, bb0); ffma2(acc[1][1], a1, bb1);
            ffma2(acc[1][2], a1, bb2); ffma2(acc[1][3], a1, bb3);
            ffma2(acc[1][4], a1, bb4); ffma2(acc[1][5], a1, bb5);
        }
        buf ^= 1;
        __syncthreads();
    }

    // ---- epilogue: rows ty*4 + 2rp (lo) / +1 (hi), cols tx*6..+5 ----
#pragma unroll
    for (int rp = 0; rp < 2; rp++) {
        int r0 = rowBase + ty * 4 + rp * 2;
        float* c0 = &Cd[(size_t)r0 * DD + colBase + tx * 6];
        float* c1 = &Cd[(size_t)(r0 + 1) * DD + colBase + tx * 6];
        float2 v;
        v.x = lo32(acc[rp][0]); v.y = lo32(acc[rp][1]); *(float2*)(c0 + 0) = v;
        v.x = lo32(acc[rp][2]); v.y = lo32(acc[rp][3]); *(float2*)(c0 + 2) = v;
        v.x = lo32(acc[rp][4]); v.y = lo32(acc[rp][5]); *(float2*)(c0 + 4) = v;
        v.x = hi32(acc[rp][0]); v.y = hi32(acc[rp][1]); *(float2*)(c1 + 0) = v;
        v.x = hi32(acc[rp][2]); v.y = hi32(acc[rp][3]); *(float2*)(c1 + 2) = v;
        v.x = hi32(acc[rp][4]); v.y = hi32(acc[rp][5]); *(float2*)(c1 + 4) = v;
    }

    // ---- fused hs/ts plane copy for this block's (row, col) tile ----
    {
        const float4* emb4 = (const float4*)g_e_emb;
        float4* out4 = (float4*)out;
        size_t P4 = (size_t)n * RR * (DD / 4);
        // tile = 64 rows x 24 float4 cols = 1536 float4 per plane; 6 per thread
#pragma unroll
        for (int s = 0; s < 6; s++) {
            int idx = tid + s * GT;        // 0..1535
            int row = idx / 24;            // 0..63
            int c4  = idx % 24;
            int b = i * RR + rowBase + row;
            int ha = hts[b * 2 + 0];
            int ta = hts[b * 2 + 1];
            int col4 = colBase / 4 + c4;
            float4 vh = emb4[(size_t)(i * EE + ha) * (DD / 4) + col4];
            float4 vt = emb4[(size_t)(i * EE + ta) * (DD / 4) + col4];
            out4[(size_t)b * (DD / 4) + col4]      = vh;
            out4[P4 + (size_t)b * (DD / 4) + col4] = vt;
        }
    }
}

// ---------------------------------------------------------------------------
extern "C" void kernel_launch(void* const* d_in, const int* in_sizes, int n_in,
                              void* d_out, int out_size)
{
    const float* seq  = (const float*)d_in[0];   // (n, L, d)
    const float* att  = (const float*)d_in[1];   // (n, h, L, L)
    const int*   pos  = (const int*)  d_in[2];   // (n, E, M)
    const float* mask = (const float*)d_in[3];   // (n, E, M)
    const int*   hts  = (const int*)  d_in[4];   // (n, R, 2)
    float* out = (float*)d_out;

    int n = in_sizes[0] / (LN * DD);
    if (n > NMAX) n = NMAX;

    {   // e_emb
        int total = n * EE * DD;
        k_e_emb<<<(total + 255) / 256, 256>>>(seq, pos, mask, n);
    }
    {   // e_att (float4)
        int total = n * EE * HH * (LN / 4);
        k_e_att<<<(total + 255) / 256, 256>>>(att, pos, mask, n);
    }
    {   // ht_att
        k_ht_att<<<n * RR, 256>>>(hts, n);
    }
    {   // rs plane GEMM (f32x2) + fused hs/ts copy
        dim3 grid(DD / BNg, RR / BMg, n);
        k_gemm<<<grid, GT>>>(seq, hts, out, n);
    }
}